// round 4
// baseline (speedup 1.0000x reference)
#include <cuda_runtime.h>
#include <math.h>

// Shapes fixed by the reference problem.
#define B_DIM 32
#define T_DIM 8192
#define C_DIM 256
#define CHUNKS 64                // T split across blocks
#define TCHUNK (T_DIM / CHUNKS)  // 128 t per chunk
#define TLANES 4                 // t-lanes per block
#define ITERS (TCHUNK / TLANES)  // 32 sequential t-steps per thread
#define CG 64                    // c-groups (of 4 channels) per block
#define NSTAT 5                  // S1, S2, S3, S4, Sp
#define EPSF 1e-6

// Partial sums, coalesced layout: [NSTAT][CHUNKS][B][C]  (10.5 MB)
__device__ float g_scratch[NSTAT * CHUNKS * B_DIM * C_DIM];
// Completion counters, one per batch. Zero-initialized; reset by last block.
__device__ int g_count[B_DIM];

// ---- packed f32x2 helpers --------------------------------------------------
__device__ __forceinline__ unsigned long long mul2(unsigned long long a,
                                                   unsigned long long b) {
    unsigned long long d;
    asm("mul.rn.f32x2 %0, %1, %2;" : "=l"(d) : "l"(a), "l"(b));
    return d;
}
__device__ __forceinline__ unsigned long long add2(unsigned long long a,
                                                   unsigned long long b) {
    unsigned long long d;
    asm("add.rn.f32x2 %0, %1, %2;" : "=l"(d) : "l"(a), "l"(b));
    return d;
}
__device__ __forceinline__ unsigned long long fma2(unsigned long long a,
                                                   unsigned long long b,
                                                   unsigned long long c) {
    unsigned long long d;
    asm("fma.rn.f32x2 %0, %1, %2, %3;" : "=l"(d) : "l"(a), "l"(b), "l"(c));
    return d;
}
__device__ __forceinline__ unsigned long long pack2(float lo, float hi) {
    unsigned long long r;
    asm("mov.b64 %0, {%1, %2};" : "=l"(r) : "f"(lo), "f"(hi));
    return r;
}
__device__ __forceinline__ void unpack2(unsigned long long v, float& lo, float& hi) {
    asm("mov.b64 {%0, %1}, %2;" : "=f"(lo), "=f"(hi) : "l"(v));
}
// ----------------------------------------------------------------------------

__global__ __launch_bounds__(256, 5)
void hom_fused(const float* __restrict__ x, const float* __restrict__ p,
               float* __restrict__ out)
{
    const int chunk = blockIdx.x;
    const int b     = blockIdx.y;
    const int tid   = threadIdx.x;
    const int cg    = tid & 63;      // 0..63 channel group
    const int tlane = tid >> 6;      // 0..3

    const float pv = p[0];
    const bool p_is_one = (pv == 1.0f);

    // base element offset: x[b, chunk*TCHUNK + tlane, cg*4]
    const float* ptr = x + ((size_t)b * T_DIM + (size_t)chunk * TCHUNK + tlane) * C_DIM
                         + cg * 4;
    const size_t step = (size_t)TLANES * C_DIM;   // advance 4 t-rows (in floats)

    // Pair accumulators: *xy holds channels {c,c+1}, *zw holds {c+2,c+3}.
    unsigned long long s1xy = 0ull, s1zw = 0ull;
    unsigned long long s2xy = 0ull, s2zw = 0ull;
    unsigned long long s3xy = 0ull, s3zw = 0ull;
    unsigned long long s4xy = 0ull, s4zw = 0ull;
    unsigned long long spxy = 0ull, spzw = 0ull;

    if (p_is_one) {
        #pragma unroll 8
        for (int i = 0; i < ITERS; ++i) {
            const ulonglong2 v = *reinterpret_cast<const ulonglong2*>(
                ptr + (size_t)i * step);
            const unsigned long long vxy = v.x, vzw = v.y;
            const unsigned long long x2xy = mul2(vxy, vxy);
            const unsigned long long x2zw = mul2(vzw, vzw);
            s1xy = add2(s1xy, vxy);          s1zw = add2(s1zw, vzw);
            s2xy = add2(s2xy, x2xy);         s2zw = add2(s2zw, x2zw);
            s3xy = fma2(x2xy, vxy, s3xy);    s3zw = fma2(x2zw, vzw, s3zw);
            s4xy = fma2(x2xy, x2xy, s4xy);   s4zw = fma2(x2zw, x2zw, s4zw);
        }
        spxy = s1xy; spzw = s1zw;   // mean(x^1) == mean(x)
    } else {
        // Generic power path: same packed accumulators (register-lean).
        #pragma unroll 4
        for (int i = 0; i < ITERS; ++i) {
            const ulonglong2 v = *reinterpret_cast<const ulonglong2*>(
                ptr + (size_t)i * step);
            const unsigned long long vxy = v.x, vzw = v.y;
            const unsigned long long x2xy = mul2(vxy, vxy);
            const unsigned long long x2zw = mul2(vzw, vzw);
            s1xy = add2(s1xy, vxy);          s1zw = add2(s1zw, vzw);
            s2xy = add2(s2xy, x2xy);         s2zw = add2(s2zw, x2zw);
            s3xy = fma2(x2xy, vxy, s3xy);    s3zw = fma2(x2zw, vzw, s3zw);
            s4xy = fma2(x2xy, x2xy, s4xy);   s4zw = fma2(x2zw, x2zw, s4zw);
            float ax, ay, az, aw;
            unpack2(vxy, ax, ay);
            unpack2(vzw, az, aw);
            spxy = add2(spxy, pack2(__powf(ax, pv), __powf(ay, pv)));
            spzw = add2(spzw, pack2(__powf(az, pv), __powf(aw, pv)));
        }
    }

    // Stage per-thread sums in shared: sm[tlane][cg][stat*4+sub]
    __shared__ float sm[TLANES][CG][NSTAT * 4];
    {
        float* dst = sm[tlane][cg];
        unpack2(s1xy, dst[ 0], dst[ 1]); unpack2(s1zw, dst[ 2], dst[ 3]);
        unpack2(s2xy, dst[ 4], dst[ 5]); unpack2(s2zw, dst[ 6], dst[ 7]);
        unpack2(s3xy, dst[ 8], dst[ 9]); unpack2(s3zw, dst[10], dst[11]);
        unpack2(s4xy, dst[12], dst[13]); unpack2(s4zw, dst[14], dst[15]);
        unpack2(spxy, dst[16], dst[17]); unpack2(spzw, dst[18], dst[19]);
    }
    __syncthreads();

    // Thread tid owns channel c = tid. Reduce the 4 t-lanes and write the
    // coalesced [stat][chunk][b][c] partials.
    {
        const int c   = tid;
        const int cgq = c >> 2;
        const int sub = c & 3;
        #pragma unroll
        for (int stat = 0; stat < NSTAT; ++stat) {
            const int j = stat * 4 + sub;
            const float v = sm[0][cgq][j] + sm[1][cgq][j]
                          + sm[2][cgq][j] + sm[3][cgq][j];
            g_scratch[((size_t)(stat * CHUNKS + chunk) * B_DIM + b) * C_DIM + c] = v;
        }
    }

    // ---- last-block-done final reduction for this batch ----
    __threadfence();              // make this block's partials globally visible
    __syncthreads();
    __shared__ int is_last;
    if (tid == 0) {
        const int old = atomicAdd(&g_count[b], 1);
        is_last = (old == CHUNKS - 1);
    }
    __syncthreads();

    if (is_last) {
        __threadfence();          // acquire: see all other blocks' partials
        const int c = tid;        // one channel per thread

        float S[NSTAT];
        #pragma unroll
        for (int s = 0; s < NSTAT; ++s) S[s] = 0.f;

        const size_t bc = (size_t)b * C_DIM + c;
        #pragma unroll 8
        for (int ch = 0; ch < CHUNKS; ++ch) {
            #pragma unroll
            for (int s = 0; s < NSTAT; ++s) {
                S[s] += g_scratch[((size_t)(s * CHUNKS + ch) * B_DIM * C_DIM) + bc];
            }
        }

        const double invT = 1.0 / (double)T_DIM;
        const double mu  = (double)S[0] * invT;
        const double m2r = (double)S[1] * invT;   // E[x^2]
        const double m3r = (double)S[2] * invT;   // E[x^3]
        const double m4r = (double)S[3] * invT;   // E[x^4]
        const double grp = (double)S[4] * invT;

        const double mu2 = mu * mu;
        const double var = m2r - mu2;
        const double m3  = m3r - 3.0 * mu * m2r + 2.0 * mu * mu2;
        const double m4  = m4r - 4.0 * mu * m3r + 6.0 * mu2 * m2r - 3.0 * mu2 * mu2;

        const double ve   = var + (double)EPSF;
        const double std_ = sqrt(ve);
        const double skew = m3 / (ve * std_);   // std^3
        const double kurt = m4 / (ve * ve);     // std^4

        float* o = out + (size_t)b * (4 * C_DIM);
        o[c]             = (float)grp;
        o[C_DIM + c]     = (float)var;
        o[2 * C_DIM + c] = (float)skew;
        o[3 * C_DIM + c] = (float)kurt;

        if (tid == 0) g_count[b] = 0;   // reset for next graph replay
    }
}

extern "C" void kernel_launch(void* const* d_in, const int* in_sizes, int n_in,
                              void* d_out, int out_size)
{
    const float* x = (const float*)d_in[0];
    const float* p = (const float*)d_in[1];
    float* out = (float*)d_out;

    dim3 grid(CHUNKS, B_DIM);
    hom_fused<<<grid, 256>>>(x, p, out);
}

// round 9
// speedup vs baseline: 1.3121x; 1.3121x over previous
#include <cuda_runtime.h>
#include <math.h>

// Shapes fixed by the reference problem.
#define B_DIM 32
#define T_DIM 8192
#define C_DIM 256
#define CHUNKS 16                // T split across blocks (fat CTAs)
#define TCHUNK (T_DIM / CHUNKS)  // 512 t per chunk
#define TLANES 4                 // t-lanes per block
#define ITERS (TCHUNK / TLANES)  // 128 sequential t-steps per thread
#define CG 64                    // c-groups (of 4 channels) per block
#define NSTAT 5                  // S1, S2, S3, S4, Sp
#define EPSF 1e-6

// Partial sums, coalesced layout: [NSTAT][CHUNKS][B][C]  (2.6 MB)
__device__ float g_scratch[NSTAT * CHUNKS * B_DIM * C_DIM];
// Completion counters, one per batch. Zero-initialized; reset by last block.
__device__ int g_count[B_DIM];

// ---- packed f32x2 helpers --------------------------------------------------
__device__ __forceinline__ unsigned long long mul2(unsigned long long a,
                                                   unsigned long long b) {
    unsigned long long d;
    asm("mul.rn.f32x2 %0, %1, %2;" : "=l"(d) : "l"(a), "l"(b));
    return d;
}
__device__ __forceinline__ unsigned long long add2(unsigned long long a,
                                                   unsigned long long b) {
    unsigned long long d;
    asm("add.rn.f32x2 %0, %1, %2;" : "=l"(d) : "l"(a), "l"(b));
    return d;
}
__device__ __forceinline__ unsigned long long fma2(unsigned long long a,
                                                   unsigned long long b,
                                                   unsigned long long c) {
    unsigned long long d;
    asm("fma.rn.f32x2 %0, %1, %2, %3;" : "=l"(d) : "l"(a), "l"(b), "l"(c));
    return d;
}
__device__ __forceinline__ unsigned long long pack2(float lo, float hi) {
    unsigned long long r;
    asm("mov.b64 %0, {%1, %2};" : "=l"(r) : "f"(lo), "f"(hi));
    return r;
}
__device__ __forceinline__ void unpack2(unsigned long long v, float& lo, float& hi) {
    asm("mov.b64 {%0, %1}, %2;" : "=f"(lo), "=f"(hi) : "l"(v));
}
// ----------------------------------------------------------------------------

__global__ __launch_bounds__(256, 5)
void hom_fused(const float* __restrict__ x, const float* __restrict__ p,
               float* __restrict__ out)
{
    const int chunk = blockIdx.x;
    const int b     = blockIdx.y;
    const int tid   = threadIdx.x;
    const int cg    = tid & 63;      // 0..63 channel group
    const int tlane = tid >> 6;      // 0..3

    const float pv = p[0];
    const bool p_is_one = (pv == 1.0f);

    // base element offset: x[b, chunk*TCHUNK + tlane, cg*4]
    const float* ptr = x + ((size_t)b * T_DIM + (size_t)chunk * TCHUNK + tlane) * C_DIM
                         + cg * 4;
    const size_t step = (size_t)TLANES * C_DIM;   // advance 4 t-rows (in floats)

    // Pair accumulators: *xy holds channels {c,c+1}, *zw holds {c+2,c+3}.
    unsigned long long s1xy = 0ull, s1zw = 0ull;
    unsigned long long s2xy = 0ull, s2zw = 0ull;
    unsigned long long s3xy = 0ull, s3zw = 0ull;
    unsigned long long s4xy = 0ull, s4zw = 0ull;
    unsigned long long spxy = 0ull, spzw = 0ull;

    if (p_is_one) {
        #pragma unroll 8
        for (int i = 0; i < ITERS; ++i) {
            const ulonglong2 v = *reinterpret_cast<const ulonglong2*>(
                ptr + (size_t)i * step);
            const unsigned long long vxy = v.x, vzw = v.y;
            const unsigned long long x2xy = mul2(vxy, vxy);
            const unsigned long long x2zw = mul2(vzw, vzw);
            s1xy = add2(s1xy, vxy);          s1zw = add2(s1zw, vzw);
            s2xy = add2(s2xy, x2xy);         s2zw = add2(s2zw, x2zw);
            s3xy = fma2(x2xy, vxy, s3xy);    s3zw = fma2(x2zw, vzw, s3zw);
            s4xy = fma2(x2xy, x2xy, s4xy);   s4zw = fma2(x2zw, x2zw, s4zw);
        }
        spxy = s1xy; spzw = s1zw;   // mean(x^1) == mean(x)
    } else {
        // Generic power path: same packed accumulators (register-lean).
        #pragma unroll 4
        for (int i = 0; i < ITERS; ++i) {
            const ulonglong2 v = *reinterpret_cast<const ulonglong2*>(
                ptr + (size_t)i * step);
            const unsigned long long vxy = v.x, vzw = v.y;
            const unsigned long long x2xy = mul2(vxy, vxy);
            const unsigned long long x2zw = mul2(vzw, vzw);
            s1xy = add2(s1xy, vxy);          s1zw = add2(s1zw, vzw);
            s2xy = add2(s2xy, x2xy);         s2zw = add2(s2zw, x2zw);
            s3xy = fma2(x2xy, vxy, s3xy);    s3zw = fma2(x2zw, vzw, s3zw);
            s4xy = fma2(x2xy, x2xy, s4xy);   s4zw = fma2(x2zw, x2zw, s4zw);
            float ax, ay, az, aw;
            unpack2(vxy, ax, ay);
            unpack2(vzw, az, aw);
            spxy = add2(spxy, pack2(__powf(ax, pv), __powf(ay, pv)));
            spzw = add2(spzw, pack2(__powf(az, pv), __powf(aw, pv)));
        }
    }

    // Stage per-thread sums in shared: sm[tlane][cg][stat*4+sub]
    __shared__ float sm[TLANES][CG][NSTAT * 4];
    {
        float* dst = sm[tlane][cg];
        unpack2(s1xy, dst[ 0], dst[ 1]); unpack2(s1zw, dst[ 2], dst[ 3]);
        unpack2(s2xy, dst[ 4], dst[ 5]); unpack2(s2zw, dst[ 6], dst[ 7]);
        unpack2(s3xy, dst[ 8], dst[ 9]); unpack2(s3zw, dst[10], dst[11]);
        unpack2(s4xy, dst[12], dst[13]); unpack2(s4zw, dst[14], dst[15]);
        unpack2(spxy, dst[16], dst[17]); unpack2(spzw, dst[18], dst[19]);
    }
    __syncthreads();

    // Thread tid owns channel c = tid. Reduce the 4 t-lanes and write the
    // coalesced [stat][chunk][b][c] partials.
    {
        const int c   = tid;
        const int cgq = c >> 2;
        const int sub = c & 3;
        #pragma unroll
        for (int stat = 0; stat < NSTAT; ++stat) {
            const int j = stat * 4 + sub;
            const float v = sm[0][cgq][j] + sm[1][cgq][j]
                          + sm[2][cgq][j] + sm[3][cgq][j];
            g_scratch[((size_t)(stat * CHUNKS + chunk) * B_DIM + b) * C_DIM + c] = v;
        }
    }

    // ---- last-block-done final reduction for this batch ----
    __threadfence();              // make this block's partials globally visible
    __syncthreads();
    __shared__ int is_last;
    if (tid == 0) {
        const int old = atomicAdd(&g_count[b], 1);
        is_last = (old == CHUNKS - 1);
    }
    __syncthreads();

    if (is_last) {
        __threadfence();          // acquire: see all other blocks' partials
        const int c = tid;        // one channel per thread

        float S[NSTAT];
        #pragma unroll
        for (int s = 0; s < NSTAT; ++s) S[s] = 0.f;

        const size_t bc = (size_t)b * C_DIM + c;
        #pragma unroll 8
        for (int ch = 0; ch < CHUNKS; ++ch) {
            #pragma unroll
            for (int s = 0; s < NSTAT; ++s) {
                S[s] += g_scratch[((size_t)(s * CHUNKS + ch) * B_DIM * C_DIM) + bc];
            }
        }

        const double invT = 1.0 / (double)T_DIM;
        const double mu  = (double)S[0] * invT;
        const double m2r = (double)S[1] * invT;   // E[x^2]
        const double m3r = (double)S[2] * invT;   // E[x^3]
        const double m4r = (double)S[3] * invT;   // E[x^4]
        const double grp = (double)S[4] * invT;

        const double mu2 = mu * mu;
        const double var = m2r - mu2;
        const double m3  = m3r - 3.0 * mu * m2r + 2.0 * mu * mu2;
        const double m4  = m4r - 4.0 * mu * m3r + 6.0 * mu2 * m2r - 3.0 * mu2 * mu2;

        const double ve   = var + (double)EPSF;
        const double std_ = sqrt(ve);
        const double skew = m3 / (ve * std_);   // std^3
        const double kurt = m4 / (ve * ve);     // std^4

        float* o = out + (size_t)b * (4 * C_DIM);
        o[c]             = (float)grp;
        o[C_DIM + c]     = (float)var;
        o[2 * C_DIM + c] = (float)skew;
        o[3 * C_DIM + c] = (float)kurt;

        if (tid == 0) g_count[b] = 0;   // reset for next graph replay
    }
}

extern "C" void kernel_launch(void* const* d_in, const int* in_sizes, int n_in,
                              void* d_out, int out_size)
{
    const float* x = (const float*)d_in[0];
    const float* p = (const float*)d_in[1];
    float* out = (float*)d_out;

    dim3 grid(CHUNKS, B_DIM);
    hom_fused<<<grid, 256>>>(x, p, out);
}